// round 12
// baseline (speedup 1.0000x reference)
#include <cuda_runtime.h>
#include <cuda_fp16.h>
#include <cstdint>

#define E_TOTAL 300000
#define TILE_M  64
#define NTH     256

// ---------------- shared memory byte offsets ----------------
#define A1B(s)   ((s) * 5120)               // 3 stages: 64 rows x 80B (32 fp16 + pad)
#define LDA1BY   80
#define GSB      0                           // fp32 64 x 50, overlays A ring post-GEMM1
#define LDGS     50
#define YHB      15360                       // fp16 64 x 24 (48B rows)
#define LDYBY    48
#define H1HB     18432                       // fp16 64 x 136 (272B rows)
#define LDHBY    272
#define S2B      18432                       // fp16 residual overlays H1h per-pass
#define LDS2BY   272
#define B1BB     35840                       // fp32 b1[128]
#define B2EB     36352                       // fp32 b2e[192]
#define BOBB     37120                       // fp32 bo[128]
#define SMEM_BYTES 37632                     // x3 CTA = 113KB; L1D keeps ~115KB (weights resident)

// ---------------- device-global prepped weights (fp16, per-warp fragment order) ------
// GEMM1 B frags: [kc(12)][wn(4)][q(4: ks*2+p)][lane(32)] x uint4
__device__ __align__(16) unsigned g_w1f[6144 * 4];
// GEMM2 B frags: [kc(4)][wn(4)][q(6: ks*3+p)][lane(32)] x uint4
__device__ __align__(16) unsigned g_w2f[3072 * 4];
// GEMM3 wo frags: [wn(2)][p(4)][lane(32)] x uint4
__device__ __align__(16) unsigned g_wof[256 * 4];
__device__ float g_b2e[192];

// ---------------- helpers ----------------
__device__ __forceinline__ unsigned packh(float lo, float hi) {
    __half2 h = __halves2half2(__float2half_rn(lo), __float2half_rn(hi));
    return *(unsigned*)&h;
}
__device__ __forceinline__ uint32_t smem_u32(const void* p) {
    uint32_t a;
    asm("{ .reg .u64 t; cvta.to.shared.u64 t, %1; cvt.u32.u64 %0, t; }" : "=r"(a) : "l"(p));
    return a;
}
__device__ __forceinline__ void ldsm4(unsigned* d, uint32_t addr) {
    asm volatile("ldmatrix.sync.aligned.m8n8.x4.shared.b16 {%0,%1,%2,%3}, [%4];"
                 : "=r"(d[0]), "=r"(d[1]), "=r"(d[2]), "=r"(d[3]) : "r"(addr));
}
__device__ __forceinline__ void mma16(float* c, const unsigned* a, unsigned b0, unsigned b1) {
    asm volatile(
        "mma.sync.aligned.m16n8k16.row.col.f32.f16.f16.f32 "
        "{%0,%1,%2,%3}, {%4,%5,%6,%7}, {%8,%9}, {%0,%1,%2,%3};"
        : "+f"(c[0]), "+f"(c[1]), "+f"(c[2]), "+f"(c[3])
        : "r"(a[0]), "r"(a[1]), "r"(a[2]), "r"(a[3]), "r"(b0), "r"(b1));
}

// ---------------- single prep kernel ----------------
__device__ float w2e_at(int n, int k, const float* w2,
                        const float* wg, const float* wt, const float* wp) {
    if (n < 128) return w2[k * 128 + n];
    if (n >= 176) return 0.f;
    int p = (n - 128) >> 4, j = (n - 128) & 15;
    const float* W = (p == 0) ? wg : (p == 1) ? wt : wp;
    float s = 0.f;
    for (int m = 0; m < 128; m++) s += w2[k * 128 + m] * W[m * 16 + j];
    return s;
}

#define W1F_N 6144
#define W2F_N 3072
#define WOF_N 256
#define B2E_N 192

__global__ void prep_all(const float* __restrict__ w1, const float* __restrict__ w2,
                         const float* __restrict__ b2,
                         const float* __restrict__ wg, const float* __restrict__ bg,
                         const float* __restrict__ wt, const float* __restrict__ bt,
                         const float* __restrict__ wp, const float* __restrict__ bp,
                         const float* __restrict__ wo) {
    int gid = blockIdx.x * 128 + threadIdx.x;
    if (gid < W1F_N) {
        int u = gid, lane = u & 31, r = u >> 5;           // r 0..191
        int q  = r & 3;
        int p  = q & 1;
        int ks = q >> 1;
        int wn = (r >> 2) & 3;
        int kc = r >> 4;                                   // 0..11
        int n0 = wn * 32 + p * 16 + (lane >> 2);
        int kb = kc * 32 + ks * 16 + 2 * (lane & 3);
        unsigned* o = g_w1f + u * 4;
        o[0] = packh(w1[kb * 128 + n0],       w1[(kb + 1) * 128 + n0]);
        o[1] = packh(w1[(kb + 8) * 128 + n0], w1[(kb + 9) * 128 + n0]);
        o[2] = packh(w1[kb * 128 + n0 + 8],       w1[(kb + 1) * 128 + n0 + 8]);
        o[3] = packh(w1[(kb + 8) * 128 + n0 + 8], w1[(kb + 9) * 128 + n0 + 8]);
    } else if (gid < W1F_N + W2F_N) {
        int u = gid - W1F_N, lane = u & 31, r = u >> 5;   // r 0..95
        int q  = r % 6;
        int ks = q / 3;
        int p  = q % 3;
        int wn = (r / 6) & 3;
        int kc = r / 24;                                   // 0..3
        int n0 = wn * 48 + p * 16 + (lane >> 2);
        int kb = kc * 32 + ks * 16 + 2 * (lane & 3);
        unsigned* o = g_w2f + u * 4;
        o[0] = packh(w2e_at(n0, kb, w2, wg, wt, wp),     w2e_at(n0, kb + 1, w2, wg, wt, wp));
        o[1] = packh(w2e_at(n0, kb + 8, w2, wg, wt, wp), w2e_at(n0, kb + 9, w2, wg, wt, wp));
        o[2] = packh(w2e_at(n0 + 8, kb, w2, wg, wt, wp),     w2e_at(n0 + 8, kb + 1, w2, wg, wt, wp));
        o[3] = packh(w2e_at(n0 + 8, kb + 8, w2, wg, wt, wp), w2e_at(n0 + 8, kb + 9, w2, wg, wt, wp));
    } else if (gid < W1F_N + W2F_N + WOF_N) {
        int u = gid - W1F_N - W2F_N, lane = u & 31, r = u >> 5;  // 0..7
        int p  = r & 3;
        int wn = r >> 2;
        int n0 = wn * 64 + p * 16 + (lane >> 2);
        int kb = 2 * (lane & 3);
        unsigned* o = g_wof + u * 4;
        o[0] = packh(wo[kb * 128 + n0],       wo[(kb + 1) * 128 + n0]);
        o[1] = packh(wo[(kb + 8) * 128 + n0], wo[(kb + 9) * 128 + n0]);
        o[2] = packh(wo[kb * 128 + n0 + 8],       wo[(kb + 1) * 128 + n0 + 8]);
        o[3] = packh(wo[(kb + 8) * 128 + n0 + 8], wo[(kb + 9) * 128 + n0 + 8]);
    } else if (gid < W1F_N + W2F_N + WOF_N + B2E_N) {
        int n = gid - W1F_N - W2F_N - WOF_N;
        float b = 0.f;
        if (n < 128) b = b2[n];
        else if (n < 176) {
            int p = (n - 128) >> 4, j = (n - 128) & 15;
            const float* W = (p == 0) ? wg : (p == 1) ? wt : wp;
            const float* B = (p == 0) ? bg : (p == 1) ? bt : bp;
            b = B[j];
            for (int m = 0; m < 128; m++) b += b2[m] * W[m * 16 + j];
        }
        g_b2e[n] = b;
    }
}

// ---------------- main fused kernel: 64 edges/CTA, 256 threads, 3 CTA/SM ----------------
extern __shared__ char smc[];

__global__ void __launch_bounds__(NTH, 3)
edge_att_kernel(const float* __restrict__ src, const float* __restrict__ tgt,
                const float* __restrict__ ea,
                const float* __restrict__ b1v, const float* __restrict__ bo,
                float* __restrict__ out) {
    const int tid  = threadIdx.x;
    const int lane = tid & 31;
    const int wid  = tid >> 5;       // 8 warps: 2M(32 rows) x 4N
    const int wm   = wid & 1;
    const int wn   = wid >> 1;
    const int row0 = wm * 32;
    const long e0  = (long)blockIdx.x * TILE_M;
    const uint32_t sbase = smem_u32(smc);
    float* smf = (float*)smc;

    // persistent biases (fp32)
    if (tid < 128) smf[B1BB / 4 + tid] = b1v[tid];
    if (tid < 128) smf[BOBB / 4 + tid] = bo[tid];
    if (tid < 192) smf[B2EB / 4 + tid] = g_b2e[tid];

    const uint4* __restrict__ w1p = ((const uint4*)g_w1f) + wn * 128 + lane;  // +kc*512, +q*32
    const uint4* __restrict__ w2p = ((const uint4*)g_w2f) + wn * 192 + lane;  // +kc*768, +q*32

    // ---- A staging (LDG fp32 -> pack fp16 -> STS) ----
    auto ldgA = [&](int kc, float4* pr) {     // k32 chunk: 64 rows x 32 fp32
        const float* sp = (kc < 4) ? src : (kc < 8) ? tgt : ea;
        int cin = (kc & 3) * 32;
#pragma unroll
        for (int i = 0; i < 2; i++) {
            int f = tid + i * NTH;
            int r = f >> 3, c4 = f & 7;
            long e = e0 + r; if (e >= E_TOTAL) e = E_TOTAL - 1;
            pr[i] = *(const float4*)(sp + e * 128 + cin + c4 * 4);
        }
    };
    auto stsA = [&](int kc, const float4* pr) {
        char* base = smc + A1B(kc % 3);
#pragma unroll
        for (int i = 0; i < 2; i++) {
            int f = tid + i * NTH;
            int r = f >> 3, c4 = f & 7;
            uint2 h;
            h.x = packh(pr[i].x, pr[i].y);
            h.y = packh(pr[i].z, pr[i].w);
            *(uint2*)(base + r * LDA1BY + c4 * 8) = h;
        }
    };
    auto ldgB1 = [&](int kc, uint4* d) {
        const uint4* p = w1p + kc * 512;
#pragma unroll
        for (int q = 0; q < 4; q++) d[q] = p[q * 32];
    };
    auto ldgB2 = [&](int kc, uint4* d) {
        const uint4* p = w2p + kc * 768;
#pragma unroll
        for (int q = 0; q < 6; q++) d[q] = p[q * 32];
    };

    // ================= GEMM1: H1 = relu(X @ w1 + b1), K=384 (12 x k32) ================
    float acc1[2][4][4];
#pragma unroll
    for (int mt = 0; mt < 2; mt++)
#pragma unroll
        for (int nt = 0; nt < 4; nt++)
#pragma unroll
            for (int q = 0; q < 4; q++) acc1[mt][nt][q] = 0.f;

    float4 pa[2];
    uint4 bq[4];
    ldgA(0, pa); stsA(0, pa);
    ldgB1(0, bq);

#pragma unroll
    for (int kc = 0; kc < 12; kc++) {
        __syncthreads();               // A stage kc visible to all warps
        if (kc + 1 < 12) ldgA(kc + 1, pa);   // issue next-chunk LDG early

        const uint32_t Ab = sbase + A1B(kc % 3);
#pragma unroll
        for (int ks = 0; ks < 2; ks++) {
            unsigned a0[4], a1[4];
            uint32_t ab = Ab + (row0 + (lane & 15)) * LDA1BY + ((lane >> 4) << 4) + ks * 32;
            ldsm4(a0, ab);
            ldsm4(a1, ab + 16 * LDA1BY);
#pragma unroll
            for (int p = 0; p < 2; p++) {
                uint4 bv = bq[ks * 2 + p];
                mma16(acc1[0][2 * p],     a0, bv.x, bv.y);
                mma16(acc1[0][2 * p + 1], a0, bv.z, bv.w);
                mma16(acc1[1][2 * p],     a1, bv.x, bv.y);
                mma16(acc1[1][2 * p + 1], a1, bv.z, bv.w);
            }
        }
        if (kc + 1 < 12) {
            ldgB1(kc + 1, bq);         // bq consumed; reload
            stsA(kc + 1, pa);          // stage (kc+1)%3 safe: readers 2 barriers back
        }
    }

    // ---- epilogue 1: H1h = fp16(relu(acc + b1)), stride 272B (conflict-free) ----
    {
        const int col0 = wn * 32;
#pragma unroll
        for (int mt = 0; mt < 2; mt++)
#pragma unroll
            for (int nt = 0; nt < 4; nt++) {
                int r = row0 + mt * 16 + (lane >> 2);
                int c = col0 + nt * 8 + (lane & 3) * 2;
                float bb0 = smf[B1BB / 4 + c], bb1 = smf[B1BB / 4 + c + 1];
                *(unsigned*)(smc + H1HB + r * LDHBY + c * 2) =
                    packh(fmaxf(acc1[mt][nt][0] + bb0, 0.f), fmaxf(acc1[mt][nt][1] + bb1, 0.f));
                *(unsigned*)(smc + H1HB + (r + 8) * LDHBY + c * 2) =
                    packh(fmaxf(acc1[mt][nt][2] + bb0, 0.f), fmaxf(acc1[mt][nt][3] + bb1, 0.f));
            }
    }
    __syncthreads();   // H1h visible

    // ================= GEMM2: two sequential 16-row passes, N=192, K=128 ==============
    // pass h: warp rows [row0 + h*16, +16); acc 24 regs, single B buffer 24 regs
#pragma unroll
    for (int h = 0; h < 2; h++) {
        float acc2[6][4];
#pragma unroll
        for (int nt = 0; nt < 6; nt++)
#pragma unroll
            for (int q = 0; q < 4; q++) acc2[nt][q] = 0.f;

        uint4 bq2[6];
#pragma unroll
        for (int kc = 0; kc < 4; kc++) {
            ldgB2(kc, bq2);
#pragma unroll
            for (int ks = 0; ks < 2; ks++) {
                unsigned a0[4];
                uint32_t ab = sbase + H1HB + (row0 + h * 16 + (lane & 15)) * LDHBY +
                              ((lane >> 4) << 4) + kc * 64 + ks * 32;
                ldsm4(a0, ab);
#pragma unroll
                for (int p = 0; p < 3; p++) {
                    uint4 bv = bq2[ks * 3 + p];
                    mma16(acc2[2 * p],     a0, bv.x, bv.y);
                    mma16(acc2[2 * p + 1], a0, bv.z, bv.w);
                }
            }
        }
        __syncthreads();   // all pass-h H1h reads done (every warp) before overlay writes

        // ---- epilogue 2 (pass h): S2h fp16 overlays H1h rows; GS fp32 ----
#pragma unroll
        for (int nt = 0; nt < 6; nt++) {
            int r = row0 + h * 16 + (lane >> 2);
            int c = wn * 48 + nt * 8 + (lane & 3) * 2;
            float bb0 = smf[B2EB / 4 + c], bb1 = smf[B2EB / 4 + c + 1];
            float v0 = acc2[nt][0] + bb0, v1 = acc2[nt][1] + bb1;
            float v2 = acc2[nt][2] + bb0, v3 = acc2[nt][3] + bb1;
            if (c < 128) {
                *(unsigned*)(smc + S2B + r * LDS2BY + c * 2)       = packh(v0, v1);
                *(unsigned*)(smc + S2B + (r + 8) * LDS2BY + c * 2) = packh(v2, v3);
            } else if (c < 176) {
                int cc = c - 128;
                *(float2*)&smf[GSB / 4 + r * LDGS + cc]       = make_float2(v0, v1);
                *(float2*)&smf[GSB / 4 + (r + 8) * LDGS + cc] = make_float2(v2, v3);
            }
        }
    }
    __syncthreads();

    // GEMM3 wo fragments (LDG, latency hidden behind softmax)
    const int wn3 = wid >> 2;
    uint4 wq[4];
    {
        const uint4* wop = ((const uint4*)g_wof) + wn3 * 128 + lane;
#pragma unroll
        for (int p = 0; p < 4; p++) wq[p] = wop[p * 32];
    }

    // ================= attention softmax: Y[r][i] = softmax_j(ph_i*th_j) . g ==========
    {
        int r = tid >> 2;                  // 0..63
        int i0 = (tid & 3) * 4;
        const float* srow = &smf[GSB / 4 + r * LDGS];
        float gg[16], th[16];
#pragma unroll
        for (int j = 0; j < 16; j++) { gg[j] = srow[j]; th[j] = srow[16 + j]; }
        float yv[4];
#pragma unroll
        for (int q = 0; q < 4; q++) {
            float ph = srow[32 + i0 + q];
            float m = ph * th[0];
#pragma unroll
            for (int j = 1; j < 16; j++) m = fmaxf(m, ph * th[j]);
            float s = 0.f, ys = 0.f;
#pragma unroll
            for (int j = 0; j < 16; j++) {
                float e = __expf(ph * th[j] - m);
                s += e; ys += e * gg[j];
            }
            yv[q] = ys / s;
        }
        uint2 h;
        h.x = packh(yv[0], yv[1]);
        h.y = packh(yv[2], yv[3]);
        *(uint2*)(smc + YHB + r * LDYBY + i0 * 2) = h;
    }
    __syncthreads();

    // ================= GEMM3: OUT = Y @ wo + bo + H2 (residual), K=16 =================
    {
        const int row0g = (wid & 3) * 16;
        const int col0g = wn3 * 64;
        float acc3[8][4];
#pragma unroll
        for (int nt = 0; nt < 8; nt++)
#pragma unroll
            for (int q = 0; q < 4; q++) acc3[nt][q] = 0.f;

        unsigned a[4];
        ldsm4(a, sbase + YHB + (row0g + (lane & 15)) * LDYBY + ((lane >> 4) << 4));
#pragma unroll
        for (int p = 0; p < 4; p++) {
            mma16(acc3[2 * p],     a, wq[p].x, wq[p].y);
            mma16(acc3[2 * p + 1], a, wq[p].z, wq[p].w);
        }

#pragma unroll
        for (int nt = 0; nt < 8; nt++) {
            int r = row0g + (lane >> 2);
            int c = col0g + nt * 8 + (lane & 3) * 2;
            float bb0 = smf[BOBB / 4 + c], bb1 = smf[BOBB / 4 + c + 1];
            long e = e0 + r;
            if (e < E_TOTAL) {
                __half2 s2 = *(__half2*)(smc + S2B + r * LDS2BY + c * 2);
                float o0 = acc3[nt][0] + __low2float(s2)  + bb0;
                float o1 = acc3[nt][1] + __high2float(s2) + bb1;
                *(float2*)&out[e * 128 + c] = make_float2(o0, o1);
            }
            long e2 = e + 8;
            if (e2 < E_TOTAL) {
                __half2 s2 = *(__half2*)(smc + S2B + (r + 8) * LDS2BY + c * 2);
                float o2 = acc3[nt][2] + __low2float(s2)  + bb0;
                float o3 = acc3[nt][3] + __high2float(s2) + bb1;
                *(float2*)&out[e2 * 128 + c] = make_float2(o2, o3);
            }
        }
    }
}

extern "C" void kernel_launch(void* const* d_in, const int* in_sizes, int n_in,
                              void* d_out, int out_size) {
    const float* src = (const float*)d_in[0];
    const float* tgt = (const float*)d_in[1];
    const float* ea  = (const float*)d_in[2];
    const float* w1  = (const float*)d_in[3];
    const float* b1  = (const float*)d_in[4];
    const float* w2  = (const float*)d_in[5];
    const float* b2  = (const float*)d_in[6];
    const float* wg  = (const float*)d_in[7];
    const float* bg  = (const float*)d_in[8];
    const float* wt  = (const float*)d_in[9];
    const float* bt  = (const float*)d_in[10];
    const float* wp  = (const float*)d_in[11];
    const float* bp  = (const float*)d_in[12];
    const float* wo  = (const float*)d_in[13];
    const float* bo  = (const float*)d_in[14];
    float* out = (float*)d_out;

    cudaFuncSetAttribute(edge_att_kernel,
                         cudaFuncAttributeMaxDynamicSharedMemorySize, SMEM_BYTES);

    prep_all<<<76, 128>>>(w1, w2, b2, wg, bg, wt, bt, wp, bp, wo);

    int grid = (E_TOTAL + TILE_M - 1) / TILE_M;   // 4688
    edge_att_kernel<<<grid, NTH, SMEM_BYTES>>>(src, tgt, ea, b1, bo, out);
}

// round 13
// speedup vs baseline: 1.0596x; 1.0596x over previous
#include <cuda_runtime.h>
#include <cuda_fp16.h>
#include <cstdint>

#define E_TOTAL 300000
#define TILE_M  64
#define NTH     256

// ---------------- shared memory byte offsets ----------------
#define A32B(s)  ((s) * 8192)               // 4 stages: fp32 A chunk, 64 rows x 128B
#define A16B(s)  (32768 + (s) * 5120)       // 2 stages: fp16 A chunk, 64 rows x 80B
#define LDA1BY   80
#define GSB      0                           // fp32 64 x 50, overlays A32 ring post-GEMM1
#define LDGS     50
#define YHB      12800                       // fp16 64 x 24 (48B rows), within A32 region
#define LDYBY    48
#define H1HB     43008                       // fp16 64 x 136 (272B rows)
#define LDHBY    272
#define S2B      43008                       // fp16 residual overlays H1h after GEMM2
#define LDS2BY   272
#define B1BB     60416                       // fp32 b1[128]
#define B2EB     60928                       // fp32 b2e[192]
#define BOBB     61696                       // fp32 bo[128]
#define SMEM_BYTES 62208                     // x2 CTA = 124KB; L1D keeps ~100KB

// ---------------- device-global prepped weights (fp16, per-warp fragment order) ------
// GEMM1 B frags: [kc(12)][wn(4)][q(4: ks*2+p)][lane(32)] x uint4
__device__ __align__(16) unsigned g_w1f[6144 * 4];
// GEMM2 B frags: [kc(4)][wn(4)][q(6: ks*3+p)][lane(32)] x uint4
__device__ __align__(16) unsigned g_w2f[3072 * 4];
// GEMM3 wo frags: [wn(2)][p(4)][lane(32)] x uint4
__device__ __align__(16) unsigned g_wof[256 * 4];
__device__ float g_b2e[192];

// ---------------- helpers ----------------
__device__ __forceinline__ unsigned packh(float lo, float hi) {
    __half2 h = __halves2half2(__float2half_rn(lo), __float2half_rn(hi));
    return *(unsigned*)&h;
}
__device__ __forceinline__ uint32_t smem_u32(const void* p) {
    uint32_t a;
    asm("{ .reg .u64 t; cvta.to.shared.u64 t, %1; cvt.u32.u64 %0, t; }" : "=r"(a) : "l"(p));
    return a;
}
__device__ __forceinline__ void cp16(uint32_t s, const void* g) {
    asm volatile("cp.async.cg.shared.global [%0], [%1], 16;" :: "r"(s), "l"(g));
}
#define CP_COMMIT() asm volatile("cp.async.commit_group;" ::: "memory")
#define CP_WAIT(n)  asm volatile("cp.async.wait_group %0;" :: "n"(n) : "memory")

__device__ __forceinline__ void ldsm4(unsigned* d, uint32_t addr) {
    asm volatile("ldmatrix.sync.aligned.m8n8.x4.shared.b16 {%0,%1,%2,%3}, [%4];"
                 : "=r"(d[0]), "=r"(d[1]), "=r"(d[2]), "=r"(d[3]) : "r"(addr));
}
__device__ __forceinline__ void mma16(float* c, const unsigned* a, unsigned b0, unsigned b1) {
    asm volatile(
        "mma.sync.aligned.m16n8k16.row.col.f32.f16.f16.f32 "
        "{%0,%1,%2,%3}, {%4,%5,%6,%7}, {%8,%9}, {%0,%1,%2,%3};"
        : "+f"(c[0]), "+f"(c[1]), "+f"(c[2]), "+f"(c[3])
        : "r"(a[0]), "r"(a[1]), "r"(a[2]), "r"(a[3]), "r"(b0), "r"(b1));
}

// ---------------- single prep kernel ----------------
__device__ float w2e_at(int n, int k, const float* w2,
                        const float* wg, const float* wt, const float* wp) {
    if (n < 128) return w2[k * 128 + n];
    if (n >= 176) return 0.f;
    int p = (n - 128) >> 4, j = (n - 128) & 15;
    const float* W = (p == 0) ? wg : (p == 1) ? wt : wp;
    float s = 0.f;
    for (int m = 0; m < 128; m++) s += w2[k * 128 + m] * W[m * 16 + j];
    return s;
}

#define W1F_N 6144
#define W2F_N 3072
#define WOF_N 256
#define B2E_N 192

__global__ void prep_all(const float* __restrict__ w1, const float* __restrict__ w2,
                         const float* __restrict__ b2,
                         const float* __restrict__ wg, const float* __restrict__ bg,
                         const float* __restrict__ wt, const float* __restrict__ bt,
                         const float* __restrict__ wp, const float* __restrict__ bp,
                         const float* __restrict__ wo) {
    int gid = blockIdx.x * 128 + threadIdx.x;
    if (gid < W1F_N) {
        int u = gid, lane = u & 31, r = u >> 5;           // r 0..191
        int q  = r & 3;
        int p  = q & 1;
        int ks = q >> 1;
        int wn = (r >> 2) & 3;
        int kc = r >> 4;                                   // 0..11
        int n0 = wn * 32 + p * 16 + (lane >> 2);
        int kb = kc * 32 + ks * 16 + 2 * (lane & 3);
        unsigned* o = g_w1f + u * 4;
        o[0] = packh(w1[kb * 128 + n0],       w1[(kb + 1) * 128 + n0]);
        o[1] = packh(w1[(kb + 8) * 128 + n0], w1[(kb + 9) * 128 + n0]);
        o[2] = packh(w1[kb * 128 + n0 + 8],       w1[(kb + 1) * 128 + n0 + 8]);
        o[3] = packh(w1[(kb + 8) * 128 + n0 + 8], w1[(kb + 9) * 128 + n0 + 8]);
    } else if (gid < W1F_N + W2F_N) {
        int u = gid - W1F_N, lane = u & 31, r = u >> 5;   // r 0..95
        int q  = r % 6;
        int ks = q / 3;
        int p  = q % 3;
        int wn = (r / 6) & 3;
        int kc = r / 24;                                   // 0..3
        int n0 = wn * 48 + p * 16 + (lane >> 2);
        int kb = kc * 32 + ks * 16 + 2 * (lane & 3);
        unsigned* o = g_w2f + u * 4;
        o[0] = packh(w2e_at(n0, kb, w2, wg, wt, wp),     w2e_at(n0, kb + 1, w2, wg, wt, wp));
        o[1] = packh(w2e_at(n0, kb + 8, w2, wg, wt, wp), w2e_at(n0, kb + 9, w2, wg, wt, wp));
        o[2] = packh(w2e_at(n0 + 8, kb, w2, wg, wt, wp),     w2e_at(n0 + 8, kb + 1, w2, wg, wt, wp));
        o[3] = packh(w2e_at(n0 + 8, kb + 8, w2, wg, wt, wp), w2e_at(n0 + 8, kb + 9, w2, wg, wt, wp));
    } else if (gid < W1F_N + W2F_N + WOF_N) {
        int u = gid - W1F_N - W2F_N, lane = u & 31, r = u >> 5;  // 0..7
        int p  = r & 3;
        int wn = r >> 2;
        int n0 = wn * 64 + p * 16 + (lane >> 2);
        int kb = 2 * (lane & 3);
        unsigned* o = g_wof + u * 4;
        o[0] = packh(wo[kb * 128 + n0],       wo[(kb + 1) * 128 + n0]);
        o[1] = packh(wo[(kb + 8) * 128 + n0], wo[(kb + 9) * 128 + n0]);
        o[2] = packh(wo[kb * 128 + n0 + 8],       wo[(kb + 1) * 128 + n0 + 8]);
        o[3] = packh(wo[(kb + 8) * 128 + n0 + 8], wo[(kb + 9) * 128 + n0 + 8]);
    } else if (gid < W1F_N + W2F_N + WOF_N + B2E_N) {
        int n = gid - W1F_N - W2F_N - WOF_N;
        float b = 0.f;
        if (n < 128) b = b2[n];
        else if (n < 176) {
            int p = (n - 128) >> 4, j = (n - 128) & 15;
            const float* W = (p == 0) ? wg : (p == 1) ? wt : wp;
            const float* B = (p == 0) ? bg : (p == 1) ? bt : bp;
            b = B[j];
            for (int m = 0; m < 128; m++) b += b2[m] * W[m * 16 + j];
        }
        g_b2e[n] = b;
    }
}

// ---------------- main fused kernel: 64 edges/CTA, 256 threads, 2 CTA/SM ----------------
extern __shared__ char smc[];

__global__ void __launch_bounds__(NTH, 2)
edge_att_kernel(const float* __restrict__ src, const float* __restrict__ tgt,
                const float* __restrict__ ea,
                const float* __restrict__ b1v, const float* __restrict__ bo,
                float* __restrict__ out) {
    const int tid  = threadIdx.x;
    const int lane = tid & 31;
    const int wid  = tid >> 5;       // 8 warps: 2M(32 rows) x 4N
    const int wm   = wid & 1;
    const int wn   = wid >> 1;
    const int row0 = wm * 32;
    const long e0  = (long)blockIdx.x * TILE_M;
    const uint32_t sbase = smem_u32(smc);
    float* smf = (float*)smc;

    // persistent biases (fp32)
    if (tid < 128) smf[B1BB / 4 + tid] = b1v[tid];
    if (tid < 128) smf[BOBB / 4 + tid] = bo[tid];
    if (tid < 192) smf[B2EB / 4 + tid] = g_b2e[tid];

    const uint4* __restrict__ w1p = ((const uint4*)g_w1f) + wn * 128 + lane;  // +kc*512, +q*32
    const uint4* __restrict__ w2p = ((const uint4*)g_w2f) + wn * 192 + lane;  // +kc*768, +q*32

    // ---- A staging: cp.async fp32 -> smem ring; convert pass -> fp16 stage ----
    auto cpA = [&](int kc) {                  // k32 chunk: 64 rows x 32 fp32 = 8KB
        const float* sp = (kc < 4) ? src : (kc < 8) ? tgt : ea;
        int cin = (kc & 3) * 32;
        uint32_t sb = sbase + A32B(kc & 3);
#pragma unroll
        for (int i = 0; i < 2; i++) {
            int f = tid + i * NTH;            // 0..511 (16B units)
            int r = f >> 3, c4 = f & 7;
            long e = e0 + r; if (e >= E_TOTAL) e = E_TOTAL - 1;
            cp16(sb + r * 128 + c4 * 16, sp + e * 128 + cin + c4 * 4);
        }
    };
    auto convA = [&](int kc) {                // fp32 stage -> fp16 stage (LDS.128 + pack + STS.64)
        const char* s32 = smc + A32B(kc & 3);
        char* d16 = smc + A16B(kc & 1);
#pragma unroll
        for (int i = 0; i < 2; i++) {
            int f = tid + i * NTH;
            int r = f >> 3, c4 = f & 7;
            float4 v = *(const float4*)(s32 + r * 128 + c4 * 16);
            uint2 h;
            h.x = packh(v.x, v.y);
            h.y = packh(v.z, v.w);
            *(uint2*)(d16 + r * LDA1BY + c4 * 8) = h;
        }
    };
    auto ldgB1 = [&](int kc, uint4* d) {
        const uint4* p = w1p + kc * 512;
#pragma unroll
        for (int q = 0; q < 4; q++) d[q] = p[q * 32];
    };
    auto ldgB2 = [&](int kc, uint4* d) {
        const uint4* p = w2p + kc * 768;
#pragma unroll
        for (int q = 0; q < 6; q++) d[q] = p[q * 32];
    };

    // ================= GEMM1: H1 = relu(X @ w1 + b1), K=384 (12 x k32) ================
    float acc1[2][4][4];
#pragma unroll
    for (int mt = 0; mt < 2; mt++)
#pragma unroll
        for (int nt = 0; nt < 4; nt++)
#pragma unroll
            for (int q = 0; q < 4; q++) acc1[mt][nt][q] = 0.f;

    uint4 bq[2][4];
    // prologue: fill cp.async ring 4 deep, convert chunk 0, prefetch B
    cpA(0); CP_COMMIT();
    cpA(1); CP_COMMIT();
    cpA(2); CP_COMMIT();
    CP_WAIT(2);                     // chunk 0 landed
    convA(0);
    cpA(3); CP_COMMIT();
    ldgB1(0, bq[0]);
    ldgB1(1, bq[1]);
    __syncthreads();                // fp16 stage 0 visible

#pragma unroll
    for (int kc = 0; kc < 12; kc++) {
        const uint32_t Ab = sbase + A16B(kc & 1);
#pragma unroll
        for (int ks = 0; ks < 2; ks++) {
            unsigned a0[4], a1[4];
            uint32_t ab = Ab + (row0 + (lane & 15)) * LDA1BY + ((lane >> 4) << 4) + ks * 32;
            ldsm4(a0, ab);
            ldsm4(a1, ab + 16 * LDA1BY);
#pragma unroll
            for (int p = 0; p < 2; p++) {
                uint4 bv = bq[kc & 1][ks * 2 + p];
                mma16(acc1[0][2 * p],     a0, bv.x, bv.y);
                mma16(acc1[0][2 * p + 1], a0, bv.z, bv.w);
                mma16(acc1[1][2 * p],     a1, bv.x, bv.y);
                mma16(acc1[1][2 * p + 1], a1, bv.z, bv.w);
            }
        }
        if (kc + 2 < 12) ldgB1(kc + 2, bq[kc & 1]);
        if (kc + 1 < 12) { CP_WAIT(2); convA(kc + 1); }    // chunk kc+1 landed (depth-3)
        if (kc + 4 < 12) cpA(kc + 4);
        CP_COMMIT();
        __syncthreads();            // fp16 stage (kc+1)&1 visible; fp32 ring slot recycled safely
    }

    // ---- epilogue 1: H1h = fp16(relu(acc + b1)), stride 272B (conflict-free) ----
    uint4 bq2[2][6];
    ldgB2(0, bq2[0]);
    {
        const int col0 = wn * 32;
#pragma unroll
        for (int mt = 0; mt < 2; mt++)
#pragma unroll
            for (int nt = 0; nt < 4; nt++) {
                int r = row0 + mt * 16 + (lane >> 2);
                int c = col0 + nt * 8 + (lane & 3) * 2;
                float bb0 = smf[B1BB / 4 + c], bb1 = smf[B1BB / 4 + c + 1];
                *(unsigned*)(smc + H1HB + r * LDHBY + c * 2) =
                    packh(fmaxf(acc1[mt][nt][0] + bb0, 0.f), fmaxf(acc1[mt][nt][1] + bb1, 0.f));
                *(unsigned*)(smc + H1HB + (r + 8) * LDHBY + c * 2) =
                    packh(fmaxf(acc1[mt][nt][2] + bb0, 0.f), fmaxf(acc1[mt][nt][3] + bb1, 0.f));
            }
    }
    ldgB2(1, bq2[1]);
    __syncthreads();   // H1h visible

    // ================= GEMM2: [H2|G|TH|PH|pad] = H1 @ w2ext, N=192, K=128 =============
    // 4 x k32 chunks, B in registers -> barrier-free interior
    float acc2[2][6][4];
#pragma unroll
    for (int mt = 0; mt < 2; mt++)
#pragma unroll
        for (int nt = 0; nt < 6; nt++)
#pragma unroll
            for (int q = 0; q < 4; q++) acc2[mt][nt][q] = 0.f;

#pragma unroll
    for (int kc = 0; kc < 4; kc++) {
#pragma unroll
        for (int ks = 0; ks < 2; ks++) {
            unsigned a0[4], a1[4];
            uint32_t ab = sbase + H1HB + (row0 + (lane & 15)) * LDHBY +
                          ((lane >> 4) << 4) + kc * 64 + ks * 32;
            ldsm4(a0, ab);
            ldsm4(a1, ab + 16 * LDHBY);
#pragma unroll
            for (int p = 0; p < 3; p++) {
                uint4 bv = bq2[kc & 1][ks * 3 + p];
                mma16(acc2[0][2 * p],     a0, bv.x, bv.y);
                mma16(acc2[0][2 * p + 1], a0, bv.z, bv.w);
                mma16(acc2[1][2 * p],     a1, bv.x, bv.y);
                mma16(acc2[1][2 * p + 1], a1, bv.z, bv.w);
            }
        }
        if (kc + 2 < 4) ldgB2(kc + 2, bq2[kc & 1]);
    }
    __syncthreads();   // all H1h reads done -> safe to overlay S2h

    // ---- epilogue 2: S2h fp16 (cols<128, overlays H1h); GS fp32 (128..175) ----
#pragma unroll
    for (int mt = 0; mt < 2; mt++)
#pragma unroll
        for (int nt = 0; nt < 6; nt++) {
            int r = row0 + mt * 16 + (lane >> 2);
            int c = wn * 48 + nt * 8 + (lane & 3) * 2;
            float bb0 = smf[B2EB / 4 + c], bb1 = smf[B2EB / 4 + c + 1];
            float v0 = acc2[mt][nt][0] + bb0, v1 = acc2[mt][nt][1] + bb1;
            float v2 = acc2[mt][nt][2] + bb0, v3 = acc2[mt][nt][3] + bb1;
            if (c < 128) {
                *(unsigned*)(smc + S2B + r * LDS2BY + c * 2)       = packh(v0, v1);
                *(unsigned*)(smc + S2B + (r + 8) * LDS2BY + c * 2) = packh(v2, v3);
            } else if (c < 176) {
                int cc = c - 128;
                *(float2*)&smf[GSB / 4 + r * LDGS + cc]       = make_float2(v0, v1);
                *(float2*)&smf[GSB / 4 + (r + 8) * LDGS + cc] = make_float2(v2, v3);
            }
        }
    __syncthreads();

    // GEMM3 wo fragments (LDG, latency hidden behind softmax)
    const int wn3 = wid >> 2;
    uint4 wq[4];
    {
        const uint4* wop = ((const uint4*)g_wof) + wn3 * 128 + lane;
#pragma unroll
        for (int p = 0; p < 4; p++) wq[p] = wop[p * 32];
    }

    // ================= attention softmax: Y[r][i] = softmax_j(ph_i*th_j) . g ==========
    {
        int r = tid >> 2;                  // 0..63
        int i0 = (tid & 3) * 4;
        const float* srow = &smf[GSB / 4 + r * LDGS];
        float gg[16], th[16];
#pragma unroll
        for (int j = 0; j < 16; j++) { gg[j] = srow[j]; th[j] = srow[16 + j]; }
        float yv[4];
#pragma unroll
        for (int q = 0; q < 4; q++) {
            float ph = srow[32 + i0 + q];
            float m = ph * th[0];
#pragma unroll
            for (int j = 1; j < 16; j++) m = fmaxf(m, ph * th[j]);
            float s = 0.f, ys = 0.f;
#pragma unroll
            for (int j = 0; j < 16; j++) {
                float e = __expf(ph * th[j] - m);
                s += e; ys += e * gg[j];
            }
            yv[q] = ys / s;
        }
        uint2 h;
        h.x = packh(yv[0], yv[1]);
        h.y = packh(yv[2], yv[3]);
        *(uint2*)(smc + YHB + r * LDYBY + i0 * 2) = h;
    }
    __syncthreads();

    // ================= GEMM3: OUT = Y @ wo + bo + H2 (residual), K=16 =================
    {
        const int row0g = (wid & 3) * 16;
        const int col0g = wn3 * 64;
        float acc3[8][4];
#pragma unroll
        for (int nt = 0; nt < 8; nt++)
#pragma unroll
            for (int q = 0; q < 4; q++) acc3[nt][q] = 0.f;

        unsigned a[4];
        ldsm4(a, sbase + YHB + (row0g + (lane & 15)) * LDYBY + ((lane >> 4) << 4));
#pragma unroll
        for (int p = 0; p < 4; p++) {
            mma16(acc3[2 * p],     a, wq[p].x, wq[p].y);
            mma16(acc3[2 * p + 1], a, wq[p].z, wq[p].w);
        }

#pragma unroll
        for (int nt = 0; nt < 8; nt++) {
            int r = row0g + (lane >> 2);
            int c = col0g + nt * 8 + (lane & 3) * 2;
            float bb0 = smf[BOBB / 4 + c], bb1 = smf[BOBB / 4 + c + 1];
            long e = e0 + r;
            if (e < E_TOTAL) {
                __half2 s2 = *(__half2*)(smc + S2B + r * LDS2BY + c * 2);
                float o0 = acc3[nt][0] + __low2float(s2)  + bb0;
                float o1 = acc3[nt][1] + __high2float(s2) + bb1;
                *(float2*)&out[e * 128 + c] = make_float2(o0, o1);
            }
            long e2 = e + 8;
            if (e2 < E_TOTAL) {
                __half2 s2 = *(__half2*)(smc + S2B + (r + 8) * LDS2BY + c * 2);
                float o2 = acc3[nt][2] + __low2float(s2)  + bb0;
                float o3 = acc3[nt][3] + __high2float(s2) + bb1;
                *(float2*)&out[e2 * 128 + c] = make_float2(o2, o3);
            }
        }
    }
}

extern "C" void kernel_launch(void* const* d_in, const int* in_sizes, int n_in,
                              void* d_out, int out_size) {
    const float* src = (const float*)d_in[0];
    const float* tgt = (const float*)d_in[1];
    const float* ea  = (const float*)d_in[2];
    const float* w1  = (const float*)d_in[3];
    const float* b1  = (const float*)d_in[4];
    const float* w2  = (const float*)d_in[5];
    const float* b2  = (const float*)d_in[6];
    const float* wg  = (const float*)d_in[7];
    const float* bg  = (const float*)d_in[8];
    const float* wt  = (const float*)d_in[9];
    const float* bt  = (const float*)d_in[10];
    const float* wp  = (const float*)d_in[11];
    const float* bp  = (const float*)d_in[12];
    const float* wo  = (const float*)d_in[13];
    const float* bo  = (const float*)d_in[14];
    float* out = (float*)d_out;

    cudaFuncSetAttribute(edge_att_kernel,
                         cudaFuncAttributeMaxDynamicSharedMemorySize, SMEM_BYTES);

    prep_all<<<76, 128>>>(w1, w2, b2, wg, bg, wt, bt, wp, bp, wo);

    int grid = (E_TOTAL + TILE_M - 1) / TILE_M;   // 4688
    edge_att_kernel<<<grid, NTH, SMEM_BYTES>>>(src, tgt, ea, b1, bo, out);
}

// round 14
// speedup vs baseline: 1.1241x; 1.0608x over previous
#include <cuda_runtime.h>
#include <cuda_fp16.h>
#include <cstdint>

#define E_TOTAL 300000
#define TILE_M  64
#define NTH     256

// ---------------- shared memory byte offsets ----------------
#define A1B(s)   ((s) * 5120)               // 3 stages: 64 rows x 80B (32 fp16 + pad)
#define LDA1BY   80
#define GSB      0                           // fp32 64 x 50, overlays A ring post-GEMM1
#define LDGS     50
#define YHB      15360                       // fp16 64 x 24 (48B rows)
#define LDYBY    48
#define H1HB     18432                       // fp16 64 x 136 (272B rows)
#define LDHBY    272
#define S2B      18432                       // fp16 residual overlays H1h after GEMM2
#define LDS2BY   272
#define B1BB     35840                       // fp32 b1[128]
#define B2EB     36352                       // fp32 b2e[192]
#define BOBB     37120                       // fp32 bo[128]
#define SMEM_BYTES 37632                     // 2 CTAs/SM (reg-limited); L1D keeps ~150KB

// ---------------- device-global prepped weights (fp16, per-warp fragment order) ------
// GEMM1 B frags: [kc(12)][wn(4)][q(4: ks*2+p)][lane(32)] x uint4
__device__ __align__(16) unsigned g_w1f[6144 * 4];
// GEMM2 B frags: [kc(4)][wn(4)][q(6: ks*3+p)][lane(32)] x uint4
__device__ __align__(16) unsigned g_w2f[3072 * 4];
// GEMM3 wo frags: [wn(2)][p(4)][lane(32)] x uint4
__device__ __align__(16) unsigned g_wof[256 * 4];
// fp32 w2ext^T table [n(192)][k(128)] (n>=176 zero) + fused bias
__device__ __align__(16) float g_w2e[192 * 128];
__device__ float g_b2e[192];

// ---------------- helpers ----------------
__device__ __forceinline__ unsigned packh(float lo, float hi) {
    __half2 h = __halves2half2(__float2half_rn(lo), __float2half_rn(hi));
    return *(unsigned*)&h;
}
__device__ __forceinline__ uint32_t smem_u32(const void* p) {
    uint32_t a;
    asm("{ .reg .u64 t; cvta.to.shared.u64 t, %1; cvt.u32.u64 %0, t; }" : "=r"(a) : "l"(p));
    return a;
}
__device__ __forceinline__ void ldsm4(unsigned* d, uint32_t addr) {
    asm volatile("ldmatrix.sync.aligned.m8n8.x4.shared.b16 {%0,%1,%2,%3}, [%4];"
                 : "=r"(d[0]), "=r"(d[1]), "=r"(d[2]), "=r"(d[3]) : "r"(addr));
}
__device__ __forceinline__ void mma16(float* c, const unsigned* a, unsigned b0, unsigned b1) {
    asm volatile(
        "mma.sync.aligned.m16n8k16.row.col.f32.f16.f16.f32 "
        "{%0,%1,%2,%3}, {%4,%5,%6,%7}, {%8,%9}, {%0,%1,%2,%3};"
        : "+f"(c[0]), "+f"(c[1]), "+f"(c[2]), "+f"(c[3])
        : "r"(a[0]), "r"(a[1]), "r"(a[2]), "r"(a[3]), "r"(b0), "r"(b1));
}

// ---------------- prep kernel 1: w2ext^T table + fused bias (ILP-split chains) -------
__global__ void prep_w2e_k(const float* __restrict__ w2, const float* __restrict__ b2,
                           const float* __restrict__ wg, const float* __restrict__ bg,
                           const float* __restrict__ wt, const float* __restrict__ bt,
                           const float* __restrict__ wp, const float* __restrict__ bp) {
    int n = blockIdx.x;     // 0..191
    int k = threadIdx.x;    // 0..127
    float v = 0.f, b = 0.f;
    if (n < 128) {
        v = w2[k * 128 + n];
        b = b2[n];
    } else if (n < 176) {
        int p = (n - 128) >> 4, j = (n - 128) & 15;
        const float* W = (p == 0) ? wg : (p == 1) ? wt : wp;
        const float* B = (p == 0) ? bg : (p == 1) ? bt : bp;
        float s0 = 0.f, s1 = 0.f, s2 = 0.f, s3 = 0.f;
#pragma unroll 8
        for (int m = 0; m < 128; m += 4) {
            s0 += w2[k * 128 + m]     * W[m * 16 + j];
            s1 += w2[k * 128 + m + 1] * W[(m + 1) * 16 + j];
            s2 += w2[k * 128 + m + 2] * W[(m + 2) * 16 + j];
            s3 += w2[k * 128 + m + 3] * W[(m + 3) * 16 + j];
        }
        v = (s0 + s1) + (s2 + s3);
        if (k == 0) {
            float t0 = B[j], t1 = 0.f, t2 = 0.f, t3 = 0.f;
#pragma unroll 8
            for (int m = 0; m < 128; m += 4) {
                t0 += b2[m]     * W[m * 16 + j];
                t1 += b2[m + 1] * W[(m + 1) * 16 + j];
                t2 += b2[m + 2] * W[(m + 2) * 16 + j];
                t3 += b2[m + 3] * W[(m + 3) * 16 + j];
            }
            b = (t0 + t1) + (t2 + t3);
        }
    }
    g_w2e[n * 128 + k] = v;
    if (k == 0) g_b2e[n] = b;
}

// ---------------- prep kernel 2: fragment packing (pure lookups) ----------------
#define W1F_N 6144
#define W2F_N 3072
#define WOF_N 256

__global__ void prep_pack(const float* __restrict__ w1, const float* __restrict__ wo) {
    int gid = blockIdx.x * 128 + threadIdx.x;
    if (gid < W1F_N) {
        int u = gid, lane = u & 31, r = u >> 5;           // r 0..191
        int q  = r & 3;
        int p  = q & 1;
        int ks = q >> 1;
        int wn = (r >> 2) & 3;
        int kc = r >> 4;                                   // 0..11
        int n0 = wn * 32 + p * 16 + (lane >> 2);
        int kb = kc * 32 + ks * 16 + 2 * (lane & 3);
        unsigned* o = g_w1f + u * 4;
        o[0] = packh(w1[kb * 128 + n0],       w1[(kb + 1) * 128 + n0]);
        o[1] = packh(w1[(kb + 8) * 128 + n0], w1[(kb + 9) * 128 + n0]);
        o[2] = packh(w1[kb * 128 + n0 + 8],       w1[(kb + 1) * 128 + n0 + 8]);
        o[3] = packh(w1[(kb + 8) * 128 + n0 + 8], w1[(kb + 9) * 128 + n0 + 8]);
    } else if (gid < W1F_N + W2F_N) {
        int u = gid - W1F_N, lane = u & 31, r = u >> 5;   // r 0..95
        int q  = r % 6;
        int ks = q / 3;
        int p  = q % 3;
        int wn = (r / 6) & 3;
        int kc = r / 24;                                   // 0..3
        int n0 = wn * 48 + p * 16 + (lane >> 2);
        int kb = kc * 32 + ks * 16 + 2 * (lane & 3);
        unsigned* o = g_w2f + u * 4;
        o[0] = packh(g_w2e[n0 * 128 + kb],     g_w2e[n0 * 128 + kb + 1]);
        o[1] = packh(g_w2e[n0 * 128 + kb + 8], g_w2e[n0 * 128 + kb + 9]);
        o[2] = packh(g_w2e[(n0 + 8) * 128 + kb],     g_w2e[(n0 + 8) * 128 + kb + 1]);
        o[3] = packh(g_w2e[(n0 + 8) * 128 + kb + 8], g_w2e[(n0 + 8) * 128 + kb + 9]);
    } else if (gid < W1F_N + W2F_N + WOF_N) {
        int u = gid - W1F_N - W2F_N, lane = u & 31, r = u >> 5;  // 0..7
        int p  = r & 3;
        int wn = r >> 2;
        int n0 = wn * 64 + p * 16 + (lane >> 2);
        int kb = 2 * (lane & 3);
        unsigned* o = g_wof + u * 4;
        o[0] = packh(wo[kb * 128 + n0],       wo[(kb + 1) * 128 + n0]);
        o[1] = packh(wo[(kb + 8) * 128 + n0], wo[(kb + 9) * 128 + n0]);
        o[2] = packh(wo[kb * 128 + n0 + 8],       wo[(kb + 1) * 128 + n0 + 8]);
        o[3] = packh(wo[(kb + 8) * 128 + n0 + 8], wo[(kb + 9) * 128 + n0 + 8]);
    }
}

// ---------------- main fused kernel: 64 edges/CTA, 256 threads, 2 CTA/SM -------------
// (exact R10 structure)
extern __shared__ char smc[];

__global__ void __launch_bounds__(NTH, 2)
edge_att_kernel(const float* __restrict__ src, const float* __restrict__ tgt,
                const float* __restrict__ ea,
                const float* __restrict__ b1v, const float* __restrict__ bo,
                float* __restrict__ out) {
    const int tid  = threadIdx.x;
    const int lane = tid & 31;
    const int wid  = tid >> 5;       // 8 warps: 2M(32 rows) x 4N
    const int wm   = wid & 1;
    const int wn   = wid >> 1;
    const int row0 = wm * 32;
    const long e0  = (long)blockIdx.x * TILE_M;
    const uint32_t sbase = smem_u32(smc);
    float* smf = (float*)smc;

    // persistent biases (fp32)
    if (tid < 128) smf[B1BB / 4 + tid] = b1v[tid];
    if (tid < 128) smf[BOBB / 4 + tid] = bo[tid];
    if (tid < 192) smf[B2EB / 4 + tid] = g_b2e[tid];

    const uint4* __restrict__ w1p = ((const uint4*)g_w1f) + wn * 128 + lane;  // +kc*512, +q*32
    const uint4* __restrict__ w2p = ((const uint4*)g_w2f) + wn * 192 + lane;  // +kc*768, +q*32

    // ---- A staging (LDG fp32 -> pack fp16 -> STS) ----
    auto ldgA = [&](int kc, float4* pr) {     // k32 chunk: 64 rows x 32 fp32
        const float* sp = (kc < 4) ? src : (kc < 8) ? tgt : ea;
        int cin = (kc & 3) * 32;
#pragma unroll
        for (int i = 0; i < 2; i++) {
            int f = tid + i * NTH;
            int r = f >> 3, c4 = f & 7;
            long e = e0 + r; if (e >= E_TOTAL) e = E_TOTAL - 1;
            pr[i] = *(const float4*)(sp + e * 128 + cin + c4 * 4);
        }
    };
    auto stsA = [&](int kc, const float4* pr) {
        char* base = smc + A1B(kc % 3);
#pragma unroll
        for (int i = 0; i < 2; i++) {
            int f = tid + i * NTH;
            int r = f >> 3, c4 = f & 7;
            uint2 h;
            h.x = packh(pr[i].x, pr[i].y);
            h.y = packh(pr[i].z, pr[i].w);
            *(uint2*)(base + r * LDA1BY + c4 * 8) = h;
        }
    };
    auto ldgB1 = [&](int kc, uint4* d) {
        const uint4* p = w1p + kc * 512;
#pragma unroll
        for (int q = 0; q < 4; q++) d[q] = p[q * 32];
    };
    auto ldgB2 = [&](int kc, uint4* d) {
        const uint4* p = w2p + kc * 768;
#pragma unroll
        for (int q = 0; q < 6; q++) d[q] = p[q * 32];
    };

    // ================= GEMM1: H1 = relu(X @ w1 + b1), K=384 (12 x k32) ================
    float acc1[2][4][4];
#pragma unroll
    for (int mt = 0; mt < 2; mt++)
#pragma unroll
        for (int nt = 0; nt < 4; nt++)
#pragma unroll
            for (int q = 0; q < 4; q++) acc1[mt][nt][q] = 0.f;

    float4 pa[2][2];
    uint4 bq[2][4];
    ldgA(0, pa[0]); stsA(0, pa[0]);
    ldgA(1, pa[1]);
    ldgB1(0, bq[0]);
    ldgB1(1, bq[1]);

#pragma unroll
    for (int kc = 0; kc < 12; kc++) {
        __syncthreads();               // A stage kc visible to all warps

        const uint32_t Ab = sbase + A1B(kc % 3);
#pragma unroll
        for (int ks = 0; ks < 2; ks++) {
            unsigned a0[4], a1[4];
            uint32_t ab = Ab + (row0 + (lane & 15)) * LDA1BY + ((lane >> 4) << 4) + ks * 32;
            ldsm4(a0, ab);
            ldsm4(a1, ab + 16 * LDA1BY);
#pragma unroll
            for (int p = 0; p < 2; p++) {
                uint4 bv = bq[kc & 1][ks * 2 + p];
                mma16(acc1[0][2 * p],     a0, bv.x, bv.y);
                mma16(acc1[0][2 * p + 1], a0, bv.z, bv.w);
                mma16(acc1[1][2 * p],     a1, bv.x, bv.y);
                mma16(acc1[1][2 * p + 1], a1, bv.z, bv.w);
            }
        }
        if (kc + 2 < 12) ldgB1(kc + 2, bq[kc & 1]);
        if (kc + 1 < 12) stsA(kc + 1, pa[(kc + 1) & 1]);
        if (kc + 2 < 12) ldgA(kc + 2, pa[kc & 1]);
    }

    // prefetch GEMM2 chunk 0 while epilogue runs
    uint4 bq2[2][6];
    ldgB2(0, bq2[0]);

    // ---- epilogue 1: H1h = fp16(relu(acc + b1)), stride 272B (conflict-free) ----
    {
        const int col0 = wn * 32;
#pragma unroll
        for (int mt = 0; mt < 2; mt++)
#pragma unroll
            for (int nt = 0; nt < 4; nt++) {
                int r = row0 + mt * 16 + (lane >> 2);
                int c = col0 + nt * 8 + (lane & 3) * 2;
                float bb0 = smf[B1BB / 4 + c], bb1 = smf[B1BB / 4 + c + 1];
                *(unsigned*)(smc + H1HB + r * LDHBY + c * 2) =
                    packh(fmaxf(acc1[mt][nt][0] + bb0, 0.f), fmaxf(acc1[mt][nt][1] + bb1, 0.f));
                *(unsigned*)(smc + H1HB + (r + 8) * LDHBY + c * 2) =
                    packh(fmaxf(acc1[mt][nt][2] + bb0, 0.f), fmaxf(acc1[mt][nt][3] + bb1, 0.f));
            }
    }
    ldgB2(1, bq2[1]);
    __syncthreads();   // H1h visible

    // ================= GEMM2: [H2|G|TH|PH|pad] = H1 @ w2ext, N=192, K=128 =============
    // 4 x k32 chunks, B in registers -> barrier-free interior
    float acc2[2][6][4];
#pragma unroll
    for (int mt = 0; mt < 2; mt++)
#pragma unroll
        for (int nt = 0; nt < 6; nt++)
#pragma unroll
            for (int q = 0; q < 4; q++) acc2[mt][nt][q] = 0.f;

#pragma unroll
    for (int kc = 0; kc < 4; kc++) {
#pragma unroll
        for (int ks = 0; ks < 2; ks++) {
            unsigned a0[4], a1[4];
            uint32_t ab = sbase + H1HB + (row0 + (lane & 15)) * LDHBY +
                          ((lane >> 4) << 4) + kc * 64 + ks * 32;
            ldsm4(a0, ab);
            ldsm4(a1, ab + 16 * LDHBY);
#pragma unroll
            for (int p = 0; p < 3; p++) {
                uint4 bv = bq2[kc & 1][ks * 3 + p];
                mma16(acc2[0][2 * p],     a0, bv.x, bv.y);
                mma16(acc2[0][2 * p + 1], a0, bv.z, bv.w);
                mma16(acc2[1][2 * p],     a1, bv.x, bv.y);
                mma16(acc2[1][2 * p + 1], a1, bv.z, bv.w);
            }
        }
        if (kc + 2 < 4) ldgB2(kc + 2, bq2[kc & 1]);
    }
    __syncthreads();   // all H1h reads done -> safe to overlay S2h

    // ---- epilogue 2: S2h fp16 (cols<128, overlays H1h); GS fp32 (128..175) ----
#pragma unroll
    for (int mt = 0; mt < 2; mt++)
#pragma unroll
        for (int nt = 0; nt < 6; nt++) {
            int r = row0 + mt * 16 + (lane >> 2);
            int c = wn * 48 + nt * 8 + (lane & 3) * 2;
            float bb0 = smf[B2EB / 4 + c], bb1 = smf[B2EB / 4 + c + 1];
            float v0 = acc2[mt][nt][0] + bb0, v1 = acc2[mt][nt][1] + bb1;
            float v2 = acc2[mt][nt][2] + bb0, v3 = acc2[mt][nt][3] + bb1;
            if (c < 128) {
                *(unsigned*)(smc + S2B + r * LDS2BY + c * 2)       = packh(v0, v1);
                *(unsigned*)(smc + S2B + (r + 8) * LDS2BY + c * 2) = packh(v2, v3);
            } else if (c < 176) {
                int cc = c - 128;
                *(float2*)&smf[GSB / 4 + r * LDGS + cc]       = make_float2(v0, v1);
                *(float2*)&smf[GSB / 4 + (r + 8) * LDGS + cc] = make_float2(v2, v3);
            }
        }
    __syncthreads();

    // GEMM3 wo fragments (LDG, latency hidden behind softmax)
    const int wn3 = wid >> 2;
    uint4 wq[4];
    {
        const uint4* wop = ((const uint4*)g_wof) + wn3 * 128 + lane;
#pragma unroll
        for (int p = 0; p < 4; p++) wq[p] = wop[p * 32];
    }

    // ================= attention softmax: Y[r][i] = softmax_j(ph_i*th_j) . g ==========
    {
        int r = tid >> 2;                  // 0..63
        int i0 = (tid & 3) * 4;
        const float* srow = &smf[GSB / 4 + r * LDGS];
        float gg[16], th[16];
#pragma unroll
        for (int j = 0; j < 16; j++) { gg[j] = srow[j]; th[j] = srow[16 + j]; }
        float yv[4];
#pragma unroll
        for (int q = 0; q < 4; q++) {
            float ph = srow[32 + i0 + q];
            float m = ph * th[0];
#pragma unroll
            for (int j = 1; j < 16; j++) m = fmaxf(m, ph * th[j]);
            float s = 0.f, ys = 0.f;
#pragma unroll
            for (int j = 0; j < 16; j++) {
                float e = __expf(ph * th[j] - m);
                s += e; ys += e * gg[j];
            }
            yv[q] = ys / s;
        }
        uint2 h;
        h.x = packh(yv[0], yv[1]);
        h.y = packh(yv[2], yv[3]);
        *(uint2*)(smc + YHB + r * LDYBY + i0 * 2) = h;
    }
    __syncthreads();

    // ================= GEMM3: OUT = Y @ wo + bo + H2 (residual), K=16 =================
    {
        const int row0g = (wid & 3) * 16;
        const int col0g = wn3 * 64;
        float acc3[8][4];
#pragma unroll
        for (int nt = 0; nt < 8; nt++)
#pragma unroll
            for (int q = 0; q < 4; q++) acc3[nt][q] = 0.f;

        unsigned a[4];
        ldsm4(a, sbase + YHB + (row0g + (lane & 15)) * LDYBY + ((lane >> 4) << 4));
#pragma unroll
        for (int p = 0; p < 4; p++) {
            mma16(acc3[2 * p],     a, wq[p].x, wq[p].y);
            mma16(acc3[2 * p + 1], a, wq[p].z, wq[p].w);
        }

#pragma unroll
        for (int nt = 0; nt < 8; nt++) {
            int r = row0g + (lane >> 2);
            int c = col0g + nt * 8 + (lane & 3) * 2;
            float bb0 = smf[BOBB / 4 + c], bb1 = smf[BOBB / 4 + c + 1];
            long e = e0 + r;
            if (e < E_TOTAL) {
                __half2 s2 = *(__half2*)(smc + S2B + r * LDS2BY + c * 2);
                float o0 = acc3[nt][0] + __low2float(s2)  + bb0;
                float o1 = acc3[nt][1] + __high2float(s2) + bb1;
                *(float2*)&out[e * 128 + c] = make_float2(o0, o1);
            }
            long e2 = e + 8;
            if (e2 < E_TOTAL) {
                __half2 s2 = *(__half2*)(smc + S2B + (r + 8) * LDS2BY + c * 2);
                float o2 = acc3[nt][2] + __low2float(s2)  + bb0;
                float o3 = acc3[nt][3] + __high2float(s2) + bb1;
                *(float2*)&out[e2 * 128 + c] = make_float2(o2, o3);
            }
        }
    }
}

extern "C" void kernel_launch(void* const* d_in, const int* in_sizes, int n_in,
                              void* d_out, int out_size) {
    const float* src = (const float*)d_in[0];
    const float* tgt = (const float*)d_in[1];
    const float* ea  = (const float*)d_in[2];
    const float* w1  = (const float*)d_in[3];
    const float* b1  = (const float*)d_in[4];
    const float* w2  = (const float*)d_in[5];
    const float* b2  = (const float*)d_in[6];
    const float* wg  = (const float*)d_in[7];
    const float* bg  = (const float*)d_in[8];
    const float* wt  = (const float*)d_in[9];
    const float* bt  = (const float*)d_in[10];
    const float* wp  = (const float*)d_in[11];
    const float* bp  = (const float*)d_in[12];
    const float* wo  = (const float*)d_in[13];
    const float* bo  = (const float*)d_in[14];
    float* out = (float*)d_out;

    cudaFuncSetAttribute(edge_att_kernel,
                         cudaFuncAttributeMaxDynamicSharedMemorySize, SMEM_BYTES);

    prep_w2e_k<<<192, 128>>>(w2, b2, wg, bg, wt, bt, wp, bp);
    prep_pack<<<74, 128>>>(w1, wo);

    int grid = (E_TOTAL + TILE_M - 1) / TILE_M;   // 4688
    edge_att_kernel<<<grid, NTH, SMEM_BYTES>>>(src, tgt, ea, b1, bo, out);
}

// round 15
// speedup vs baseline: 1.1839x; 1.0532x over previous
#include <cuda_runtime.h>
#include <cuda_fp16.h>
#include <cstdint>

#define E_TOTAL 300000
#define TILE_M  64
#define NTH     256

// ---------------- shared memory byte offsets ----------------
#define A1B(s)   ((s) * 5120)               // 3 stages: 64 rows x 80B (32 fp16 + pad)
#define LDA1BY   80
#define GSB      0                           // fp32 64 x 50, overlays A ring post-GEMM1
#define LDGS     50
#define YHB      15360                       // fp16 64 x 24 (48B rows)
#define LDYBY    48
#define H1HB     18432                       // fp16 64 x 136 (272B rows)
#define LDHBY    272
#define S2B      18432                       // fp16 residual overlays H1h after GEMM2
#define LDS2BY   272
#define B1BB     35840                       // fp32 b1[128]
#define B2EB     36352                       // fp32 b2e[192]
#define BOBB     37120                       // fp32 bo[128]
#define SMEM_BYTES 37632                     // 2 CTAs/SM (reg-limited); L1D keeps ~150KB

// ---------------- device-global prepped weights (fp16, per-warp fragment order) ------
// GEMM1 B frags: [kc(12)][wn(4)][q(4: ks*2+p)][lane(32)] x uint4
__device__ __align__(16) unsigned g_w1f[6144 * 4];
// GEMM2 B frags: [kc(4)][wn(4)][q(6: ks*3+p)][lane(32)] x uint4
__device__ __align__(16) unsigned g_w2f[3072 * 4];
// GEMM3 wo frags: [wn(2)][p(4)][lane(32)] x uint4
__device__ __align__(16) unsigned g_wof[256 * 4];
// fp32 w2ext^T table [n(192)][k(128)] (n>=176 zero) + fused bias
__device__ __align__(16) float g_w2e[192 * 128];
__device__ float g_b2e[192];

// ---------------- helpers ----------------
__device__ __forceinline__ unsigned packh(float lo, float hi) {
    __half2 h = __halves2half2(__float2half_rn(lo), __float2half_rn(hi));
    return *(unsigned*)&h;
}
__device__ __forceinline__ uint32_t smem_u32(const void* p) {
    uint32_t a;
    asm("{ .reg .u64 t; cvta.to.shared.u64 t, %1; cvt.u32.u64 %0, t; }" : "=r"(a) : "l"(p));
    return a;
}
__device__ __forceinline__ void ldsm4(unsigned* d, uint32_t addr) {
    asm volatile("ldmatrix.sync.aligned.m8n8.x4.shared.b16 {%0,%1,%2,%3}, [%4];"
                 : "=r"(d[0]), "=r"(d[1]), "=r"(d[2]), "=r"(d[3]) : "r"(addr));
}
__device__ __forceinline__ void mma16(float* c, const unsigned* a, unsigned b0, unsigned b1) {
    asm volatile(
        "mma.sync.aligned.m16n8k16.row.col.f32.f16.f16.f32 "
        "{%0,%1,%2,%3}, {%4,%5,%6,%7}, {%8,%9}, {%0,%1,%2,%3};"
        : "+f"(c[0]), "+f"(c[1]), "+f"(c[2]), "+f"(c[3])
        : "r"(a[0]), "r"(a[1]), "r"(a[2]), "r"(a[3]), "r"(b0), "r"(b1));
}

// ---------------- prep kernel 1: w2ext^T table + fused bias ----------------
// Heavy n (128..175): W column staged to smem once; w2 rows streamed as float4.
__global__ void prep_w2e_k(const float* __restrict__ w2, const float* __restrict__ b2,
                           const float* __restrict__ wg, const float* __restrict__ bg,
                           const float* __restrict__ wt, const float* __restrict__ bt,
                           const float* __restrict__ wp, const float* __restrict__ bp) {
    __shared__ float Wj[128];
    int n = blockIdx.x;     // 0..191
    int k = threadIdx.x;    // 0..127
    if (n < 128) {
        g_w2e[n * 128 + k] = w2[k * 128 + n];
        if (k == 0) g_b2e[n] = b2[n];
        return;
    }
    if (n >= 176) {
        g_w2e[n * 128 + k] = 0.f;
        if (k == 0) g_b2e[n] = 0.f;
        return;
    }
    int p = (n - 128) >> 4, j = (n - 128) & 15;
    const float* W = (p == 0) ? wg : (p == 1) ? wt : wp;
    const float* B = (p == 0) ? bg : (p == 1) ? bt : bp;
    Wj[k] = W[k * 16 + j];
    __syncthreads();

    const float4* wr = (const float4*)(w2 + k * 128);
    float s0 = 0.f, s1 = 0.f, s2 = 0.f, s3 = 0.f;
#pragma unroll
    for (int m = 0; m < 32; m++) {
        float4 v = wr[m];
        s0 += v.x * Wj[4 * m];
        s1 += v.y * Wj[4 * m + 1];
        s2 += v.z * Wj[4 * m + 2];
        s3 += v.w * Wj[4 * m + 3];
    }
    g_w2e[n * 128 + k] = (s0 + s1) + (s2 + s3);

    if (k == 0) {
        float t0 = B[j], t1 = 0.f, t2 = 0.f, t3 = 0.f;
#pragma unroll
        for (int m = 0; m < 128; m += 4) {
            t0 += b2[m]     * Wj[m];
            t1 += b2[m + 1] * Wj[m + 1];
            t2 += b2[m + 2] * Wj[m + 2];
            t3 += b2[m + 3] * Wj[m + 3];
        }
        g_b2e[n] = (t0 + t1) + (t2 + t3);
    }
}

// ---------------- prep kernel 2: fragment packing (pure lookups) ----------------
#define W1F_N 6144
#define W2F_N 3072
#define WOF_N 256

__global__ void prep_pack(const float* __restrict__ w1, const float* __restrict__ wo) {
    int gid = blockIdx.x * 128 + threadIdx.x;
    if (gid < W1F_N) {
        int u = gid, lane = u & 31, r = u >> 5;           // r 0..191
        int q  = r & 3;
        int p  = q & 1;
        int ks = q >> 1;
        int wn = (r >> 2) & 3;
        int kc = r >> 4;                                   // 0..11
        int n0 = wn * 32 + p * 16 + (lane >> 2);
        int kb = kc * 32 + ks * 16 + 2 * (lane & 3);
        unsigned* o = g_w1f + u * 4;
        o[0] = packh(w1[kb * 128 + n0],       w1[(kb + 1) * 128 + n0]);
        o[1] = packh(w1[(kb + 8) * 128 + n0], w1[(kb + 9) * 128 + n0]);
        o[2] = packh(w1[kb * 128 + n0 + 8],       w1[(kb + 1) * 128 + n0 + 8]);
        o[3] = packh(w1[(kb + 8) * 128 + n0 + 8], w1[(kb + 9) * 128 + n0 + 8]);
    } else if (gid < W1F_N + W2F_N) {
        int u = gid - W1F_N, lane = u & 31, r = u >> 5;   // r 0..95
        int q  = r % 6;
        int ks = q / 3;
        int p  = q % 3;
        int wn = (r / 6) & 3;
        int kc = r / 24;                                   // 0..3
        int n0 = wn * 48 + p * 16 + (lane >> 2);
        int kb = kc * 32 + ks * 16 + 2 * (lane & 3);
        unsigned* o = g_w2f + u * 4;
        o[0] = packh(g_w2e[n0 * 128 + kb],     g_w2e[n0 * 128 + kb + 1]);
        o[1] = packh(g_w2e[n0 * 128 + kb + 8], g_w2e[n0 * 128 + kb + 9]);
        o[2] = packh(g_w2e[(n0 + 8) * 128 + kb],     g_w2e[(n0 + 8) * 128 + kb + 1]);
        o[3] = packh(g_w2e[(n0 + 8) * 128 + kb + 8], g_w2e[(n0 + 8) * 128 + kb + 9]);
    } else if (gid < W1F_N + W2F_N + WOF_N) {
        int u = gid - W1F_N - W2F_N, lane = u & 31, r = u >> 5;  // 0..7
        int p  = r & 3;
        int wn = r >> 2;
        int n0 = wn * 64 + p * 16 + (lane >> 2);
        int kb = 2 * (lane & 3);
        unsigned* o = g_wof + u * 4;
        o[0] = packh(wo[kb * 128 + n0],       wo[(kb + 1) * 128 + n0]);
        o[1] = packh(wo[(kb + 8) * 128 + n0], wo[(kb + 9) * 128 + n0]);
        o[2] = packh(wo[kb * 128 + n0 + 8],       wo[(kb + 1) * 128 + n0 + 8]);
        o[3] = packh(wo[(kb + 8) * 128 + n0 + 8], wo[(kb + 9) * 128 + n0 + 8]);
    }
}

// ---------------- main fused kernel: 64 edges/CTA, 256 threads, 2 CTA/SM -------------
// (exact R10 structure)
extern __shared__ char smc[];

__global__ void __launch_bounds__(NTH, 2)
edge_att_kernel(const float* __restrict__ src, const float* __restrict__ tgt,
                const float* __restrict__ ea,
                const float* __restrict__ b1v, const float* __restrict__ bo,
                float* __restrict__ out) {
    const int tid  = threadIdx.x;
    const int lane = tid & 31;
    const int wid  = tid >> 5;       // 8 warps: 2M(32 rows) x 4N
    const int wm   = wid & 1;
    const int wn   = wid >> 1;
    const int row0 = wm * 32;
    const long e0  = (long)blockIdx.x * TILE_M;
    const uint32_t sbase = smem_u32(smc);
    float* smf = (float*)smc;

    // persistent biases (fp32)
    if (tid < 128) smf[B1BB / 4 + tid] = b1v[tid];
    if (tid < 128) smf[BOBB / 4 + tid] = bo[tid];
    if (tid < 192) smf[B2EB / 4 + tid] = g_b2e[tid];

    const uint4* __restrict__ w1p = ((const uint4*)g_w1f) + wn * 128 + lane;  // +kc*512, +q*32
    const uint4* __restrict__ w2p = ((const uint4*)g_w2f) + wn * 192 + lane;  // +kc*768, +q*32

    // ---- A staging (LDG fp32 -> pack fp16 -> STS) ----
    auto ldgA = [&](int kc, float4* pr) {     // k32 chunk: 64 rows x 32 fp32
        const float* sp = (kc < 4) ? src : (kc < 8) ? tgt : ea;
        int cin = (kc & 3) * 32;
#pragma unroll
        for (int i = 0; i < 2; i++) {
            int f = tid + i * NTH;
            int r = f >> 3, c4 = f & 7;
            long e = e0 + r; if (e >= E_TOTAL) e = E_TOTAL - 1;
            pr[i] = *(const float4*)(sp + e * 128 + cin + c4 * 4);
        }
    };
    auto stsA = [&](int kc, const float4* pr) {
        char* base = smc + A1B(kc % 3);
#pragma unroll
        for (int i = 0; i < 2; i++) {
            int f = tid + i * NTH;
            int r = f >> 3, c4 = f & 7;
            uint2 h;
            h.x = packh(pr[i].x, pr[i].y);
            h.y = packh(pr[i].z, pr[i].w);
            *(uint2*)(base + r * LDA1BY + c4 * 8) = h;
        }
    };
    auto ldgB1 = [&](int kc, uint4* d) {
        const uint4* p = w1p + kc * 512;
#pragma unroll
        for (int q = 0; q < 4; q++) d[q] = p[q * 32];
    };
    auto ldgB2 = [&](int kc, uint4* d) {
        const uint4* p = w2p + kc * 768;
#pragma unroll
        for (int q = 0; q < 6; q++) d[q] = p[q * 32];
    };

    // ================= GEMM1: H1 = relu(X @ w1 + b1), K=384 (12 x k32) ================
    float acc1[2][4][4];
#pragma unroll
    for (int mt = 0; mt < 2; mt++)
#pragma unroll
        for (int nt = 0; nt < 4; nt++)
#pragma unroll
            for (int q = 0; q < 4; q++) acc1[mt][nt][q] = 0.f;

    float4 pa[2][2];
    uint4 bq[2][4];
    ldgA(0, pa[0]); stsA(0, pa[0]);
    ldgA(1, pa[1]);
    ldgB1(0, bq[0]);
    ldgB1(1, bq[1]);

#pragma unroll
    for (int kc = 0; kc < 12; kc++) {
        __syncthreads();               // A stage kc visible to all warps

        const uint32_t Ab = sbase + A1B(kc % 3);
#pragma unroll
        for (int ks = 0; ks < 2; ks++) {
            unsigned a0[4], a1[4];
            uint32_t ab = Ab + (row0 + (lane & 15)) * LDA1BY + ((lane >> 4) << 4) + ks * 32;
            ldsm4(a0, ab);
            ldsm4(a1, ab + 16 * LDA1BY);
#pragma unroll
            for (int p = 0; p < 2; p++) {
                uint4 bv = bq[kc & 1][ks * 2 + p];
                mma16(acc1[0][2 * p],     a0, bv.x, bv.y);
                mma16(acc1[0][2 * p + 1], a0, bv.z, bv.w);
                mma16(acc1[1][2 * p],     a1, bv.x, bv.y);
                mma16(acc1[1][2 * p + 1], a1, bv.z, bv.w);
            }
        }
        if (kc + 2 < 12) ldgB1(kc + 2, bq[kc & 1]);
        if (kc + 1 < 12) stsA(kc + 1, pa[(kc + 1) & 1]);
        if (kc + 2 < 12) ldgA(kc + 2, pa[kc & 1]);
    }

    // prefetch GEMM2 chunk 0 while epilogue runs
    uint4 bq2[2][6];
    ldgB2(0, bq2[0]);

    // ---- epilogue 1: H1h = fp16(relu(acc + b1)), stride 272B (conflict-free) ----
    {
        const int col0 = wn * 32;
#pragma unroll
        for (int mt = 0; mt < 2; mt++)
#pragma unroll
            for (int nt = 0; nt < 4; nt++) {
                int r = row0 + mt * 16 + (lane >> 2);
                int c = col0 + nt * 8 + (lane & 3) * 2;
                float bb0 = smf[B1BB / 4 + c], bb1 = smf[B1BB / 4 + c + 1];
                *(unsigned*)(smc + H1HB + r * LDHBY + c * 2) =
                    packh(fmaxf(acc1[mt][nt][0] + bb0, 0.f), fmaxf(acc1[mt][nt][1] + bb1, 0.f));
                *(unsigned*)(smc + H1HB + (r + 8) * LDHBY + c * 2) =
                    packh(fmaxf(acc1[mt][nt][2] + bb0, 0.f), fmaxf(acc1[mt][nt][3] + bb1, 0.f));
            }
    }
    ldgB2(1, bq2[1]);
    __syncthreads();   // H1h visible

    // ================= GEMM2: [H2|G|TH|PH|pad] = H1 @ w2ext, N=192, K=128 =============
    // 4 x k32 chunks, B in registers -> barrier-free interior
    float acc2[2][6][4];
#pragma unroll
    for (int mt = 0; mt < 2; mt++)
#pragma unroll
        for (int nt = 0; nt < 6; nt++)
#pragma unroll
            for (int q = 0; q < 4; q++) acc2[mt][nt][q] = 0.f;

#pragma unroll
    for (int kc = 0; kc < 4; kc++) {
#pragma unroll
        for (int ks = 0; ks < 2; ks++) {
            unsigned a0[4], a1[4];
            uint32_t ab = sbase + H1HB + (row0 + (lane & 15)) * LDHBY +
                          ((lane >> 4) << 4) + kc * 64 + ks * 32;
            ldsm4(a0, ab);
            ldsm4(a1, ab + 16 * LDHBY);
#pragma unroll
            for (int p = 0; p < 3; p++) {
                uint4 bv = bq2[kc & 1][ks * 3 + p];
                mma16(acc2[0][2 * p],     a0, bv.x, bv.y);
                mma16(acc2[0][2 * p + 1], a0, bv.z, bv.w);
                mma16(acc2[1][2 * p],     a1, bv.x, bv.y);
                mma16(acc2[1][2 * p + 1], a1, bv.z, bv.w);
            }
        }
        if (kc + 2 < 4) ldgB2(kc + 2, bq2[kc & 1]);
    }
    __syncthreads();   // all H1h reads done -> safe to overlay S2h

    // ---- epilogue 2: S2h fp16 (cols<128, overlays H1h); GS fp32 (128..175) ----
#pragma unroll
    for (int mt = 0; mt < 2; mt++)
#pragma unroll
        for (int nt = 0; nt < 6; nt++) {
            int r = row0 + mt * 16 + (lane >> 2);
            int c = wn * 48 + nt * 8 + (lane & 3) * 2;
            float bb0 = smf[B2EB / 4 + c], bb1 = smf[B2EB / 4 + c + 1];
            float v0 = acc2[mt][nt][0] + bb0, v1 = acc2[mt][nt][1] + bb1;
            float v2 = acc2[mt][nt][2] + bb0, v3 = acc2[mt][nt][3] + bb1;
            if (c < 128) {
                *(unsigned*)(smc + S2B + r * LDS2BY + c * 2)       = packh(v0, v1);
                *(unsigned*)(smc + S2B + (r + 8) * LDS2BY + c * 2) = packh(v2, v3);
            } else if (c < 176) {
                int cc = c - 128;
                *(float2*)&smf[GSB / 4 + r * LDGS + cc]       = make_float2(v0, v1);
                *(float2*)&smf[GSB / 4 + (r + 8) * LDGS + cc] = make_float2(v2, v3);
            }
        }
    __syncthreads();

    // GEMM3 wo fragments (LDG, latency hidden behind softmax)
    const int wn3 = wid >> 2;
    uint4 wq[4];
    {
        const uint4* wop = ((const uint4*)g_wof) + wn3 * 128 + lane;
#pragma unroll
        for (int p = 0; p < 4; p++) wq[p] = wop[p * 32];
    }

    // ================= attention softmax: Y[r][i] = softmax_j(ph_i*th_j) . g ==========
    {
        int r = tid >> 2;                  // 0..63
        int i0 = (tid & 3) * 4;
        const float* srow = &smf[GSB / 4 + r * LDGS];
        float gg[16], th[16];
#pragma unroll
        for (int j = 0; j < 16; j++) { gg[j] = srow[j]; th[j] = srow[16 + j]; }
        float yv[4];
#pragma unroll
        for (int q = 0; q < 4; q++) {
            float ph = srow[32 + i0 + q];
            float m = ph * th[0];
#pragma unroll
            for (int j = 1; j < 16; j++) m = fmaxf(m, ph * th[j]);
            float s = 0.f, ys = 0.f;
#pragma unroll
            for (int j = 0; j < 16; j++) {
                float e = __expf(ph * th[j] - m);
                s += e; ys += e * gg[j];
            }
            yv[q] = ys / s;
        }
        uint2 h;
        h.x = packh(yv[0], yv[1]);
        h.y = packh(yv[2], yv[3]);
        *(uint2*)(smc + YHB + r * LDYBY + i0 * 2) = h;
    }
    __syncthreads();

    // ================= GEMM3: OUT = Y @ wo + bo + H2 (residual), K=16 =================
    {
        const int row0g = (wid & 3) * 16;
        const int col0g = wn3 * 64;
        float acc3[8][4];
#pragma unroll
        for (int nt = 0; nt < 8; nt++)
#pragma unroll
            for (int q = 0; q < 4; q++) acc3[nt][q] = 0.f;

        unsigned a[4];
        ldsm4(a, sbase + YHB + (row0g + (lane & 15)) * LDYBY + ((lane >> 4) << 4));
#pragma unroll
        for (int p = 0; p < 4; p++) {
            mma16(acc3[2 * p],     a, wq[p].x, wq[p].y);
            mma16(acc3[2 * p + 1], a, wq[p].z, wq[p].w);
        }

#pragma unroll
        for (int nt = 0; nt < 8; nt++) {
            int r = row0g + (lane >> 2);
            int c = col0g + nt * 8 + (lane & 3) * 2;
            float bb0 = smf[BOBB / 4 + c], bb1 = smf[BOBB / 4 + c + 1];
            long e = e0 + r;
            if (e < E_TOTAL) {
                __half2 s2 = *(__half2*)(smc + S2B + r * LDS2BY + c * 2);
                float o0 = acc3[nt][0] + __low2float(s2)  + bb0;
                float o1 = acc3[nt][1] + __high2float(s2) + bb1;
                *(float2*)&out[e * 128 + c] = make_float2(o0, o1);
            }
            long e2 = e + 8;
            if (e2 < E_TOTAL) {
                __half2 s2 = *(__half2*)(smc + S2B + (r + 8) * LDS2BY + c * 2);
                float o2 = acc3[nt][2] + __low2float(s2)  + bb0;
                float o3 = acc3[nt][3] + __high2float(s2) + bb1;
                *(float2*)&out[e2 * 128 + c] = make_float2(o2, o3);
            }
        }
    }
}

extern "C" void kernel_launch(void* const* d_in, const int* in_sizes, int n_in,
                              void* d_out, int out_size) {
    const float* src = (const float*)d_in[0];
    const float* tgt = (const float*)d_in[1];
    const float* ea  = (const float*)d_in[2];
    const float* w1  = (const float*)d_in[3];
    const float* b1  = (const float*)d_in[4];
    const float* w2  = (const float*)d_in[5];
    const float* b2  = (const float*)d_in[6];
    const float* wg  = (const float*)d_in[7];
    const float* bg  = (const float*)d_in[8];
    const float* wt  = (const float*)d_in[9];
    const float* bt  = (const float*)d_in[10];
    const float* wp  = (const float*)d_in[11];
    const float* bp  = (const float*)d_in[12];
    const float* wo  = (const float*)d_in[13];
    const float* bo  = (const float*)d_in[14];
    float* out = (float*)d_out;

    cudaFuncSetAttribute(edge_att_kernel,
                         cudaFuncAttributeMaxDynamicSharedMemorySize, SMEM_BYTES);

    prep_w2e_k<<<192, 128>>>(w2, b2, wg, bg, wt, bt, wp, bp);
    prep_pack<<<74, 128>>>(w1, wo);

    int grid = (E_TOTAL + TILE_M - 1) / TILE_M;   // 4688
    edge_att_kernel<<<grid, NTH, SMEM_BYTES>>>(src, tgt, ea, b1, bo, out);
}